// round 1
// baseline (speedup 1.0000x reference)
#include <cuda_runtime.h>
#include <mma.h>

using namespace nvcuda;

#define DIM_IN  128
#define DIM_HID 256
#define DIM_OUT 128
#define NEXP    8
#define MAXN    65536
#define MAXROWS (2 * MAXN)
#define MAXTILES (MAXROWS / 128 + NEXP)

// ---------------- device scratch (static, allowed) ----------------
__device__ int    g_counts[NEXP];
__device__ int    g_cursor[NEXP];
__device__ int    g_numTiles;
__device__ int    g_tileExpert[MAXTILES];
__device__ int    g_tileStart[MAXTILES];
__device__ int    g_tileRows[MAXTILES];
__device__ int    g_tokE[MAXN];
__device__ float2 g_tokW[MAXN];
__device__ int    g_rowToken[MAXROWS];
__device__ float  g_rowW[MAXROWS];

// ---------------- kernel 0: zero counts ----------------
__global__ void moe_init() {
    int t = threadIdx.x;
    if (t < NEXP) g_counts[t] = 0;
}

// ---------------- kernel 1: gate ----------------
// h = x@Wp + bp ; logits = h@E ; p = sigmoid(logits/5) ; top-2 ; counts
__global__ void __launch_bounds__(256) moe_gate(
    const float* __restrict__ x, const float* __restrict__ Wp,
    const float* __restrict__ bp, const float* __restrict__ Ee,
    float* __restrict__ pout, int n)
{
    __shared__ float WpS[DIM_IN * 64];   // 128x64
    __shared__ float EeS[64 * NEXP];     // 64x8
    __shared__ float hS[8][64];
    __shared__ float pS[8][8];
    __shared__ int   cntS[NEXP];

    int tid = threadIdx.x, warp = tid >> 5, lane = tid & 31;
    for (int i = tid; i < DIM_IN * 64; i += 256) WpS[i] = Wp[i];
    for (int i = tid; i < 64 * NEXP; i += 256)   EeS[i] = Ee[i];
    if (tid < NEXP) cntS[tid] = 0;
    __syncthreads();

    for (int tok = blockIdx.x * 8 + warp; tok < n; tok += gridDim.x * 8) {
        float xr[4];
        #pragma unroll
        for (int i = 0; i < 4; i++) xr[i] = x[(long)tok * DIM_IN + lane + 32 * i];

        float h0 = bp[lane], h1 = bp[lane + 32];
        #pragma unroll
        for (int d = 0; d < DIM_IN; d++) {
            float xd = __shfl_sync(0xffffffffu, xr[d >> 5], d & 31);
            h0 += xd * WpS[d * 64 + lane];
            h1 += xd * WpS[d * 64 + lane + 32];
        }
        hS[warp][lane] = h0;
        hS[warp][lane + 32] = h1;
        __syncwarp();

        if (lane < NEXP) {
            float lg = 0.f;
            #pragma unroll
            for (int e2 = 0; e2 < 64; e2++) lg += hS[warp][e2] * EeS[e2 * NEXP + lane];
            float p = 1.f / (1.f + expf(-lg * 0.2f));   // tau = 5
            pS[warp][lane] = p;
            if (pout) pout[(long)tok * NEXP + lane] = p;
        }
        __syncwarp();

        if (lane == 0) {
            float v0 = -1.f, v1 = -1.f; int i0 = 0, i1 = 0;
            #pragma unroll
            for (int j = 0; j < NEXP; j++) {
                float pv = pS[warp][j];
                if (pv > v0) { v1 = v0; i1 = i0; v0 = pv; i0 = j; }
                else if (pv > v1) { v1 = pv; i1 = j; }
            }
            float s = v0 + v1 + 1e-10f;
            g_tokE[tok] = i0 | (i1 << 8);
            g_tokW[tok] = make_float2(v0 / s, v1 / s);
            atomicAdd(&cntS[i0], 1);
            atomicAdd(&cntS[i1], 1);
        }
        __syncwarp();
    }
    __syncthreads();
    if (tid < NEXP) atomicAdd(&g_counts[tid], cntS[tid]);
}

// ---------------- kernel 2: scan + tile map (tiny, serial) ----------------
__global__ void moe_build() {
    if (threadIdx.x == 0) {
        int off = 0, tile = 0;
        for (int e = 0; e < NEXP; e++) {
            int c = g_counts[e];
            g_cursor[e] = off;
            for (int t = 0; t < c && tile < MAXTILES; t += 128) {
                g_tileExpert[tile] = e;
                g_tileStart[tile]  = off + t;
                g_tileRows[tile]   = min(128, c - t);
                tile++;
            }
            off += c;
        }
        g_numTiles = tile;
    }
}

// ---------------- kernel 3: scatter (block-aggregated atomics) ----------------
__global__ void __launch_bounds__(256) moe_scatter(int n) {
    __shared__ int cnt[NEXP];
    __shared__ int base[NEXP];
    int tid = threadIdx.x;
    if (tid < NEXP) cnt[tid] = 0;
    __syncthreads();

    int tok = blockIdx.x * 256 + tid;
    int e0 = 0, e1 = 0, r0 = 0, r1 = 0; float2 w = make_float2(0.f, 0.f);
    bool ok = (tok < n);
    if (ok) {
        int e01 = g_tokE[tok];
        w = g_tokW[tok];
        e0 = e01 & 255; e1 = (e01 >> 8) & 255;
        r0 = atomicAdd(&cnt[e0], 1);
        r1 = atomicAdd(&cnt[e1], 1);
    }
    __syncthreads();
    if (tid < NEXP) base[tid] = atomicAdd(&g_cursor[tid], cnt[tid]);
    __syncthreads();
    if (ok) {
        int p0 = base[e0] + r0; g_rowToken[p0] = tok; g_rowW[p0] = w.x;
        int p1 = base[e1] + r1; g_rowToken[p1] = tok; g_rowW[p1] = w.y;
    }
}

// ---------------- kernel 4: grouped expert GEMM (wmma tf32, split hi/lo) ----------------
using FragA = wmma::fragment<wmma::matrix_a, 16, 16, 8, wmma::precision::tf32, wmma::row_major>;
using FragB = wmma::fragment<wmma::matrix_b, 16, 16, 8, wmma::precision::tf32, wmma::row_major>;
using FragC = wmma::fragment<wmma::accumulator, 16, 16, 8, float>;

template <class F>
__device__ __forceinline__ void split_tf32(F& hi, F& lo) {
    #pragma unroll
    for (int i = 0; i < hi.num_elements; i++) {
        float v = hi.x[i];
        float h = wmma::__float_to_tf32(v);
        hi.x[i] = h;
        lo.x[i] = wmma::__float_to_tf32(v - h);
    }
}

#define XS_LD 132
#define HS_LD 260
#define WS_LD 264
#define SMEM_BYTES ((128 * XS_LD + 128 * HS_LD + 16 * WS_LD) * 4)

__global__ void __launch_bounds__(256, 1) moe_expert(
    const float* __restrict__ x,
    const float* __restrict__ W1, const float* __restrict__ b1,
    const float* __restrict__ W2, const float* __restrict__ b2,
    float* __restrict__ out)
{
    int tile = blockIdx.x;
    if (tile >= g_numTiles) return;
    int e        = g_tileExpert[tile];
    int rowStart = g_tileStart[tile];
    int nRows    = g_tileRows[tile];

    extern __shared__ float sm[];
    float* Xs = sm;                      // 128 x 132
    float* Hs = Xs + 128 * XS_LD;        // 128 x 260
    float* Ws = Hs + 128 * HS_LD;        // 16  x 264
    __shared__ int   tokS[128];
    __shared__ float wS[128];

    int tid = threadIdx.x, warp = tid >> 5;
    int m0 = warp * 16;

    if (tid < 128) {
        int tok = -1; float w = 0.f;
        if (tid < nRows) { tok = g_rowToken[rowStart + tid]; w = g_rowW[rowStart + tid]; }
        tokS[tid] = tok; wS[tid] = w;
    }
    __syncthreads();

    // gather X tile (coalesced float4)
    for (int i = tid; i < 128 * 32; i += 256) {
        int r = i >> 5, c4 = i & 31;
        float4 v = make_float4(0.f, 0.f, 0.f, 0.f);
        int tok = tokS[r];
        if (tok >= 0) v = reinterpret_cast<const float4*>(x)[(long)tok * 32 + c4];
        *reinterpret_cast<float4*>(&Xs[r * XS_LD + c4 * 4]) = v;
    }

    const float* W1e = W1 + (long)e * DIM_IN * DIM_HID;
    const float* W2e = W2 + (long)e * DIM_HID * DIM_OUT;

    // ---- GEMM1: H[128x256] = X[128x128] @ W1e ----
    FragC acc[16];
    #pragma unroll
    for (int nt = 0; nt < 16; nt++) wmma::fill_fragment(acc[nt], 0.f);

    for (int kc = 0; kc < DIM_IN; kc += 16) {
        __syncthreads();
        for (int i = tid; i < 16 * 64; i += 256) {          // 16 rows x 256 cols
            int r = i >> 6, c4 = i & 63;
            *reinterpret_cast<float4*>(&Ws[r * WS_LD + c4 * 4]) =
                *reinterpret_cast<const float4*>(&W1e[(long)(kc + r) * DIM_HID + c4 * 4]);
        }
        __syncthreads();
        #pragma unroll
        for (int kk = 0; kk < 16; kk += 8) {
            FragA a, al;
            wmma::load_matrix_sync(a, &Xs[m0 * XS_LD + kc + kk], XS_LD);
            al = a;
            split_tf32(a, al);
            #pragma unroll
            for (int nt = 0; nt < 16; nt++) {
                FragB b, bl;
                wmma::load_matrix_sync(b, &Ws[kk * WS_LD + nt * 16], WS_LD);
                bl = b;
                split_tf32(b, bl);
                wmma::mma_sync(acc[nt], a,  b,  acc[nt]);
                wmma::mma_sync(acc[nt], al, b,  acc[nt]);
                wmma::mma_sync(acc[nt], a,  bl, acc[nt]);
            }
        }
    }
    #pragma unroll
    for (int nt = 0; nt < 16; nt++)
        wmma::store_matrix_sync(&Hs[m0 * HS_LD + nt * 16], acc[nt], HS_LD, wmma::mem_row_major);
    __syncthreads();

    // relu(H + b1)
    const float* b1e = b1 + (long)e * DIM_HID;
    for (int i = tid; i < 128 * DIM_HID; i += 256) {
        int r = i >> 8, c = i & 255;
        float v = Hs[r * HS_LD + c] + __ldg(&b1e[c]);
        Hs[r * HS_LD + c] = v > 0.f ? v : 0.f;
    }

    // ---- GEMM2: C[128x128] = H[128x256] @ W2e ----
    FragC acc2[8];
    #pragma unroll
    for (int nt = 0; nt < 8; nt++) wmma::fill_fragment(acc2[nt], 0.f);

    for (int kc = 0; kc < DIM_HID; kc += 16) {
        __syncthreads();
        for (int i = tid; i < 16 * 32; i += 256) {          // 16 rows x 128 cols
            int r = i >> 5, c4 = i & 31;
            *reinterpret_cast<float4*>(&Ws[r * WS_LD + c4 * 4]) =
                *reinterpret_cast<const float4*>(&W2e[(long)(kc + r) * DIM_OUT + c4 * 4]);
        }
        __syncthreads();
        #pragma unroll
        for (int kk = 0; kk < 16; kk += 8) {
            FragA a, al;
            wmma::load_matrix_sync(a, &Hs[m0 * HS_LD + kc + kk], HS_LD);
            al = a;
            split_tf32(a, al);
            #pragma unroll
            for (int nt = 0; nt < 8; nt++) {
                FragB b, bl;
                wmma::load_matrix_sync(b, &Ws[kk * WS_LD + nt * 16], WS_LD);
                bl = b;
                split_tf32(b, bl);
                wmma::mma_sync(acc2[nt], a,  b,  acc2[nt]);
                wmma::mma_sync(acc2[nt], al, b,  acc2[nt]);
                wmma::mma_sync(acc2[nt], a,  bl, acc2[nt]);
            }
        }
    }
    __syncthreads();
    #pragma unroll
    for (int nt = 0; nt < 8; nt++)
        wmma::store_matrix_sync(&Xs[m0 * XS_LD + nt * 16], acc2[nt], XS_LD, wmma::mem_row_major);
    __syncthreads();

    // epilogue: out[tok] += w * (C + b2)
    const float* b2e = b2 + (long)e * DIM_OUT;
    for (int i = tid; i < 128 * DIM_OUT; i += 256) {
        int r = i >> 7, c = i & 127;
        int tok = tokS[r];
        if (tok >= 0)
            atomicAdd(&out[(long)tok * DIM_OUT + c], wS[r] * (Xs[r * XS_LD + c] + __ldg(&b2e[c])));
    }
}

// ---------------- launch ----------------
extern "C" void kernel_launch(void* const* d_in, const int* in_sizes, int n_in,
                              void* d_out, int out_size) {
    const float* x  = (const float*)d_in[0];
    const float* Wp = (const float*)d_in[1];
    const float* bp = (const float*)d_in[2];
    const float* Ee = (const float*)d_in[3];
    const float* W1 = (const float*)d_in[4];
    const float* b1 = (const float*)d_in[5];
    const float* W2 = (const float*)d_in[6];
    const float* b2 = (const float*)d_in[7];
    float* out = (float*)d_out;

    int n = in_sizes[0] / DIM_IN;

    // output layout: [out (n*128)] [optional scalar] [p_open (n*8)]
    float* pout = nullptr;
    long need = (long)n * DIM_OUT + (long)n * NEXP;
    if ((long)out_size >= need) pout = out + ((long)out_size - (long)n * NEXP);

    cudaMemsetAsync(d_out, 0, (size_t)out_size * sizeof(float));

    moe_init<<<1, 32>>>();
    moe_gate<<<1024, 256>>>(x, Wp, bp, Ee, pout, n);
    moe_build<<<1, 1>>>();
    moe_scatter<<<(n + 255) / 256, 256>>>(n);

    cudaFuncSetAttribute(moe_expert, cudaFuncAttributeMaxDynamicSharedMemorySize, SMEM_BYTES);
    int tiles = (2 * n + 127) / 128 + NEXP;
    moe_expert<<<tiles, 256, SMEM_BYTES>>>(x, W1, b1, W2, b2, out);
}

// round 2
// speedup vs baseline: 1.1420x; 1.1420x over previous
#include <cuda_runtime.h>
#include <cuda_bf16.h>
#include <mma.h>

using namespace nvcuda;

#define DIM_IN  128
#define DIM_HID 256
#define DIM_OUT 128
#define NEXP    8
#define MAXN    65536
#define MAXROWS (2 * MAXN)
#define MAXTILES (MAXROWS / 128 + NEXP)

// ---------------- device scratch (static, allowed) ----------------
__device__ int    g_counts[NEXP];
__device__ int    g_cursor[NEXP];
__device__ int    g_numTiles;
__device__ int    g_tileExpert[MAXTILES];
__device__ int    g_tileStart[MAXTILES];
__device__ int    g_tileRows[MAXTILES];
__device__ int    g_tokE[MAXN];
__device__ float2 g_tokW[MAXN];
__device__ int    g_rowToken[MAXROWS];
__device__ float  g_rowW[MAXROWS];

// ---------------- kernel 0: zero counts ----------------
__global__ void moe_init() {
    int t = threadIdx.x;
    if (t < NEXP) g_counts[t] = 0;
}

// ---------------- kernel 1: gate ----------------
__global__ void __launch_bounds__(256) moe_gate(
    const float* __restrict__ x, const float* __restrict__ Wp,
    const float* __restrict__ bp, const float* __restrict__ Ee,
    float* __restrict__ pout, int n)
{
    __shared__ float WpS[DIM_IN * 64];
    __shared__ float EeS[64 * NEXP];
    __shared__ float hS[8][64];
    __shared__ float pS[8][8];
    __shared__ int   cntS[NEXP];

    int tid = threadIdx.x, warp = tid >> 5, lane = tid & 31;
    for (int i = tid; i < DIM_IN * 64; i += 256) WpS[i] = Wp[i];
    for (int i = tid; i < 64 * NEXP; i += 256)   EeS[i] = Ee[i];
    if (tid < NEXP) cntS[tid] = 0;
    __syncthreads();

    for (int tok = blockIdx.x * 8 + warp; tok < n; tok += gridDim.x * 8) {
        float xr[4];
        #pragma unroll
        for (int i = 0; i < 4; i++) xr[i] = x[(long)tok * DIM_IN + lane + 32 * i];

        float h0 = bp[lane], h1 = bp[lane + 32];
        #pragma unroll
        for (int d = 0; d < DIM_IN; d++) {
            float xd = __shfl_sync(0xffffffffu, xr[d >> 5], d & 31);
            h0 += xd * WpS[d * 64 + lane];
            h1 += xd * WpS[d * 64 + lane + 32];
        }
        hS[warp][lane] = h0;
        hS[warp][lane + 32] = h1;
        __syncwarp();

        if (lane < NEXP) {
            float lg = 0.f;
            #pragma unroll
            for (int e2 = 0; e2 < 64; e2++) lg += hS[warp][e2] * EeS[e2 * NEXP + lane];
            float p = 1.f / (1.f + expf(-lg * 0.2f));   // tau = 5
            pS[warp][lane] = p;
            if (pout) pout[(long)tok * NEXP + lane] = p;
        }
        __syncwarp();

        if (lane == 0) {
            float v0 = -1.f, v1 = -1.f; int i0 = 0, i1 = 0;
            #pragma unroll
            for (int j = 0; j < NEXP; j++) {
                float pv = pS[warp][j];
                if (pv > v0) { v1 = v0; i1 = i0; v0 = pv; i0 = j; }
                else if (pv > v1) { v1 = pv; i1 = j; }
            }
            float s = v0 + v1 + 1e-10f;
            g_tokE[tok] = i0 | (i1 << 8);
            g_tokW[tok] = make_float2(v0 / s, v1 / s);
            atomicAdd(&cntS[i0], 1);
            atomicAdd(&cntS[i1], 1);
        }
        __syncwarp();
    }
    __syncthreads();
    if (tid < NEXP) atomicAdd(&g_counts[tid], cntS[tid]);
}

// ---------------- kernel 2: scan + tile map ----------------
__global__ void moe_build() {
    if (threadIdx.x == 0) {
        int off = 0, tile = 0;
        for (int e = 0; e < NEXP; e++) {
            int c = g_counts[e];
            g_cursor[e] = off;
            for (int t = 0; t < c && tile < MAXTILES; t += 128) {
                g_tileExpert[tile] = e;
                g_tileStart[tile]  = off + t;
                g_tileRows[tile]   = min(128, c - t);
                tile++;
            }
            off += c;
        }
        g_numTiles = tile;
    }
}

// ---------------- kernel 3: scatter ----------------
__global__ void __launch_bounds__(256) moe_scatter(int n) {
    __shared__ int cnt[NEXP];
    __shared__ int base[NEXP];
    int tid = threadIdx.x;
    if (tid < NEXP) cnt[tid] = 0;
    __syncthreads();

    int tok = blockIdx.x * 256 + tid;
    int e0 = 0, e1 = 0, r0 = 0, r1 = 0; float2 w = make_float2(0.f, 0.f);
    bool ok = (tok < n);
    if (ok) {
        int e01 = g_tokE[tok];
        w = g_tokW[tok];
        e0 = e01 & 255; e1 = (e01 >> 8) & 255;
        r0 = atomicAdd(&cnt[e0], 1);
        r1 = atomicAdd(&cnt[e1], 1);
    }
    __syncthreads();
    if (tid < NEXP) base[tid] = atomicAdd(&g_cursor[tid], cnt[tid]);
    __syncthreads();
    if (ok) {
        int p0 = base[e0] + r0; g_rowToken[p0] = tok; g_rowW[p0] = w.x;
        int p1 = base[e1] + r1; g_rowToken[p1] = tok; g_rowW[p1] = w.y;
    }
}

// ---------------- kernel 4: grouped expert GEMM (3xBF16 split) ----------------
using FragA = wmma::fragment<wmma::matrix_a, 16, 16, 16, __nv_bfloat16, wmma::row_major>;
using FragB = wmma::fragment<wmma::matrix_b, 16, 16, 16, __nv_bfloat16, wmma::row_major>;
using FragC = wmma::fragment<wmma::accumulator, 16, 16, 16, float>;

__device__ __forceinline__ void bsplit(float v, __nv_bfloat16& hi, __nv_bfloat16& lo) {
    hi = __float2bfloat16_rn(v);
    lo = __float2bfloat16_rn(v - __bfloat162float(hi));
}

#define LDA 136   // bf16 ld for X / W2-chunk planes (128 rows)
#define LDB 264   // bf16 ld for W1 / H planes (128 rows)
#define STAGE_LD 132
#define SMEM_BYTES ((2 * 128 * LDA + 2 * 128 * LDB) * 2)   // 204800 B

__global__ void __launch_bounds__(256, 1) moe_expert(
    const float* __restrict__ x,
    const float* __restrict__ W1, const float* __restrict__ b1,
    const float* __restrict__ W2, const float* __restrict__ b2,
    float* __restrict__ out)
{
    int tile = blockIdx.x;
    if (tile >= g_numTiles) return;
    int e        = g_tileExpert[tile];
    int rowStart = g_tileStart[tile];
    int nRows    = g_tileRows[tile];

    extern __shared__ __align__(16) unsigned char smraw[];
    __nv_bfloat16* sAhi = (__nv_bfloat16*)smraw;           // 128 x LDA  (X / W2 chunks)
    __nv_bfloat16* sAlo = sAhi + 128 * LDA;
    __nv_bfloat16* sBhi = sAlo + 128 * LDA;                // 128 x LDB  (W1 / H)
    __nv_bfloat16* sBlo = sBhi + 128 * LDB;
    float*         stageF = (float*)smraw;                 // aliases sA region (>=128x132 f32)

    __shared__ int   tokS[128];
    __shared__ float wS[128];

    int tid = threadIdx.x, warp = tid >> 5;
    int m0 = warp * 16;

    if (tid < 128) {
        int tok = -1; float w = 0.f;
        if (tid < nRows) { tok = g_rowToken[rowStart + tid]; w = g_rowW[rowStart + tid]; }
        tokS[tid] = tok; wS[tid] = w;
    }
    __syncthreads();

    const float* W1e = W1 + (long)e * DIM_IN * DIM_HID;
    const float* W2e = W2 + (long)e * DIM_HID * DIM_OUT;
    const float* b1e = b1 + (long)e * DIM_HID;
    const float* b2e = b2 + (long)e * DIM_OUT;

    // ---- fill X (gathered) and full W1, bf16 hi/lo split ----
    #pragma unroll 4
    for (int i = tid; i < 128 * 32; i += 256) {            // X: 128x128
        int r = i >> 5, c4 = i & 31;
        float4 v = make_float4(0.f, 0.f, 0.f, 0.f);
        int tok = tokS[r];
        if (tok >= 0) v = reinterpret_cast<const float4*>(x)[(long)tok * 32 + c4];
        int o = r * LDA + c4 * 4;
        bsplit(v.x, sAhi[o+0], sAlo[o+0]);
        bsplit(v.y, sAhi[o+1], sAlo[o+1]);
        bsplit(v.z, sAhi[o+2], sAlo[o+2]);
        bsplit(v.w, sAhi[o+3], sAlo[o+3]);
    }
    #pragma unroll 4
    for (int i = tid; i < 128 * 64; i += 256) {            // W1: 128(K) x 256(N)
        int r = i >> 6, c4 = i & 63;
        float4 v = *reinterpret_cast<const float4*>(&W1e[(long)r * DIM_HID + c4 * 4]);
        int o = r * LDB + c4 * 4;
        bsplit(v.x, sBhi[o+0], sBlo[o+0]);
        bsplit(v.y, sBhi[o+1], sBlo[o+1]);
        bsplit(v.z, sBhi[o+2], sBlo[o+2]);
        bsplit(v.w, sBhi[o+3], sBlo[o+3]);
    }
    __syncthreads();

    // ---- GEMM1: H[128x256] = X @ W1  (no inner barriers) ----
    FragC acc[16];
    #pragma unroll
    for (int nt = 0; nt < 16; nt++) wmma::fill_fragment(acc[nt], 0.f);

    #pragma unroll
    for (int ks = 0; ks < 8; ks++) {                       // k = ks*16
        FragA ahi, alo;
        wmma::load_matrix_sync(ahi, &sAhi[m0 * LDA + ks * 16], LDA);
        wmma::load_matrix_sync(alo, &sAlo[m0 * LDA + ks * 16], LDA);
        #pragma unroll
        for (int nt = 0; nt < 16; nt++) {
            FragB bhi, blo;
            wmma::load_matrix_sync(bhi, &sBhi[(ks * 16) * LDB + nt * 16], LDB);
            wmma::load_matrix_sync(blo, &sBlo[(ks * 16) * LDB + nt * 16], LDB);
            wmma::mma_sync(acc[nt], ahi, bhi, acc[nt]);
            wmma::mma_sync(acc[nt], ahi, blo, acc[nt]);
            wmma::mma_sync(acc[nt], alo, bhi, acc[nt]);
        }
    }
    __syncthreads();   // W1 fully consumed; X fully consumed

    // ---- H = relu(acc + b1): stage fp32 through sA area, split-bf16 into sB ----
    #pragma unroll
    for (int h = 0; h < 2; h++) {
        #pragma unroll
        for (int nt = 0; nt < 8; nt++)
            wmma::store_matrix_sync(&stageF[m0 * STAGE_LD + nt * 16], acc[h * 8 + nt],
                                    STAGE_LD, wmma::mem_row_major);
        __syncthreads();
        for (int i = tid; i < 128 * 128; i += 256) {
            int r = i >> 7, c = i & 127;
            float v = stageF[r * STAGE_LD + c] + __ldg(&b1e[h * 128 + c]);
            v = v > 0.f ? v : 0.f;
            int o = r * LDB + h * 128 + c;
            bsplit(v, sBhi[o], sBlo[o]);
        }
        __syncthreads();
    }

    // ---- GEMM2: C[128x128] = H[128x256] @ W2, double-buffered 64-row chunks ----
    FragC acc2[8];
    #pragma unroll
    for (int nt = 0; nt < 8; nt++) wmma::fill_fragment(acc2[nt], 0.f);

    // preload chunk 0 into buf 0 (rows [0,64) of sA planes)
    #pragma unroll 2
    for (int i = tid; i < 64 * 32; i += 256) {
        int r = i >> 5, c4 = i & 31;
        float4 v = *reinterpret_cast<const float4*>(&W2e[(long)r * DIM_OUT + c4 * 4]);
        int o = r * LDA + c4 * 4;
        bsplit(v.x, sAhi[o+0], sAlo[o+0]);
        bsplit(v.y, sAhi[o+1], sAlo[o+1]);
        bsplit(v.z, sAhi[o+2], sAlo[o+2]);
        bsplit(v.w, sAhi[o+3], sAlo[o+3]);
    }
    __syncthreads();

    #pragma unroll
    for (int c = 0; c < 4; c++) {
        // issue next chunk's loads into the other buffer half
        if (c < 3) {
            int nb = (c + 1) & 1;
            int k0 = (c + 1) * 64;
            #pragma unroll 2
            for (int i = tid; i < 64 * 32; i += 256) {
                int r = i >> 5, c4 = i & 31;
                float4 v = *reinterpret_cast<const float4*>(&W2e[(long)(k0 + r) * DIM_OUT + c4 * 4]);
                int o = (nb * 64 + r) * LDA + c4 * 4;
                bsplit(v.x, sAhi[o+0], sAlo[o+0]);
                bsplit(v.y, sAhi[o+1], sAlo[o+1]);
                bsplit(v.z, sAhi[o+2], sAlo[o+2]);
                bsplit(v.w, sAhi[o+3], sAlo[o+3]);
            }
        }
        int buf = c & 1;
        #pragma unroll
        for (int ks = 0; ks < 4; ks++) {                   // k = c*64 + ks*16
            FragA ahi, alo;
            wmma::load_matrix_sync(ahi, &sBhi[m0 * LDB + c * 64 + ks * 16], LDB);
            wmma::load_matrix_sync(alo, &sBlo[m0 * LDB + c * 64 + ks * 16], LDB);
            #pragma unroll
            for (int nt = 0; nt < 8; nt++) {
                FragB bhi, blo;
                wmma::load_matrix_sync(bhi, &sAhi[(buf * 64 + ks * 16) * LDA + nt * 16], LDA);
                wmma::load_matrix_sync(blo, &sAlo[(buf * 64 + ks * 16) * LDA + nt * 16], LDA);
                wmma::mma_sync(acc2[nt], ahi, bhi, acc2[nt]);
                wmma::mma_sync(acc2[nt], ahi, blo, acc2[nt]);
                wmma::mma_sync(acc2[nt], alo, bhi, acc2[nt]);
            }
        }
        __syncthreads();
    }

    // ---- epilogue: out[tok] += w * (C + b2) ----
    #pragma unroll
    for (int nt = 0; nt < 8; nt++)
        wmma::store_matrix_sync(&stageF[m0 * STAGE_LD + nt * 16], acc2[nt],
                                STAGE_LD, wmma::mem_row_major);
    __syncthreads();

    for (int i = tid; i < 128 * DIM_OUT; i += 256) {
        int r = i >> 7, c = i & 127;
        int tok = tokS[r];
        if (tok >= 0)
            atomicAdd(&out[(long)tok * DIM_OUT + c],
                      wS[r] * (stageF[r * STAGE_LD + c] + __ldg(&b2e[c])));
    }
}

// ---------------- launch ----------------
extern "C" void kernel_launch(void* const* d_in, const int* in_sizes, int n_in,
                              void* d_out, int out_size) {
    const float* x  = (const float*)d_in[0];
    const float* Wp = (const float*)d_in[1];
    const float* bp = (const float*)d_in[2];
    const float* Ee = (const float*)d_in[3];
    const float* W1 = (const float*)d_in[4];
    const float* b1 = (const float*)d_in[5];
    const float* W2 = (const float*)d_in[6];
    const float* b2 = (const float*)d_in[7];
    float* out = (float*)d_out;

    int n = in_sizes[0] / DIM_IN;

    float* pout = nullptr;
    long need = (long)n * DIM_OUT + (long)n * NEXP;
    if ((long)out_size >= need) pout = out + ((long)out_size - (long)n * NEXP);

    cudaMemsetAsync(d_out, 0, (size_t)out_size * sizeof(float));

    moe_init<<<1, 32>>>();
    moe_gate<<<1024, 256>>>(x, Wp, bp, Ee, pout, n);
    moe_build<<<1, 1>>>();
    moe_scatter<<<(n + 255) / 256, 256>>>(n);

    cudaFuncSetAttribute(moe_expert, cudaFuncAttributeMaxDynamicSharedMemorySize, SMEM_BYTES);
    int tiles = (2 * n + 127) / 128 + NEXP;
    moe_expert<<<tiles, 256, SMEM_BYTES>>>(x, W1, b1, W2, b2, out);
}

// round 7
// speedup vs baseline: 2.0938x; 1.8334x over previous
#include <cuda_runtime.h>
#include <cuda_bf16.h>
#include <mma.h>
#include <cstdint>

using namespace nvcuda;

#define DIM_IN  128
#define DIM_HID 256
#define DIM_OUT 128
#define NEXP    8
#define MAXN    65536
#define MAXROWS (2 * MAXN)
#define MAXTILES (MAXROWS / 128 + NEXP)

// ---------------- device scratch ----------------
__device__ int    g_counts[NEXP];
__device__ int    g_cursor[NEXP];
__device__ int    g_numTiles;
__device__ int    g_tileExpert[MAXTILES];
__device__ int    g_tileStart[MAXTILES];
__device__ int    g_tileRows[MAXTILES];
__device__ int    g_tokE[MAXN];
__device__ float2 g_tokW[MAXN];
__device__ int    g_rowToken[MAXROWS];
__device__ float  g_rowW[MAXROWS];

__device__ __align__(16) __nv_bfloat16 g_xhi[MAXN * DIM_IN];
__device__ __align__(16) __nv_bfloat16 g_xlo[MAXN * DIM_IN];
__device__ __align__(16) __nv_bfloat16 g_w1hi[NEXP * DIM_IN * DIM_HID];  // [e][k=128][n=256]
__device__ __align__(16) __nv_bfloat16 g_w1lo[NEXP * DIM_IN * DIM_HID];
__device__ __align__(16) __nv_bfloat16 g_w2hi[NEXP * DIM_HID * DIM_OUT]; // [e][k=256][n=128]
__device__ __align__(16) __nv_bfloat16 g_w2lo[NEXP * DIM_HID * DIM_OUT];

__device__ __forceinline__ uint32_t pack2(float a, float b) {
    __nv_bfloat16 h0 = __float2bfloat16_rn(a);
    __nv_bfloat16 h1 = __float2bfloat16_rn(b);
    return (uint32_t)__bfloat16_as_ushort(h0) | ((uint32_t)__bfloat16_as_ushort(h1) << 16);
}
__device__ __forceinline__ uint32_t pack2lo(float a, float b, uint32_t hi) {
    float h0 = __bfloat162float(__ushort_as_bfloat16((unsigned short)(hi & 0xFFFF)));
    float h1 = __bfloat162float(__ushort_as_bfloat16((unsigned short)(hi >> 16)));
    return pack2(a - h0, b - h1);
}

// ---------------- kernel: weight bf16 split (same layout) + zero counts ----------------
// grid 512 x 256: each thread converts one float4 of W1 and one of W2
__global__ void __launch_bounds__(256) moe_prep(
    const float* __restrict__ W1, const float* __restrict__ W2)
{
    int idx = blockIdx.x * 256 + threadIdx.x;          // 0 .. 131071
    if (blockIdx.x == 0 && threadIdx.x < NEXP) g_counts[threadIdx.x] = 0;
    if (idx < 65536) {                                  // W1: 262144 floats = 65536 float4
        float4 v = reinterpret_cast<const float4*>(W1)[idx];
        uint32_t h0 = pack2(v.x, v.y), h1 = pack2(v.z, v.w);
        uint32_t l0 = pack2lo(v.x, v.y, h0), l1 = pack2lo(v.z, v.w, h1);
        reinterpret_cast<uint2*>(g_w1hi)[idx] = make_uint2(h0, h1);
        reinterpret_cast<uint2*>(g_w1lo)[idx] = make_uint2(l0, l1);

        float4 w = reinterpret_cast<const float4*>(W2)[idx];
        uint32_t g0 = pack2(w.x, w.y), g1 = pack2(w.z, w.w);
        uint32_t m0 = pack2lo(w.x, w.y, g0), m1 = pack2lo(w.z, w.w, g1);
        reinterpret_cast<uint2*>(g_w2hi)[idx] = make_uint2(g0, g1);
        reinterpret_cast<uint2*>(g_w2lo)[idx] = make_uint2(m0, m1);
    }
}

// ---------------- kernel: gate (+ X bf16 split + output zeroing) ----------------
__global__ void __launch_bounds__(256) moe_gate(
    const float* __restrict__ x, const float* __restrict__ Wp,
    const float* __restrict__ bp, const float* __restrict__ Ee,
    float* __restrict__ outbuf, long zero_lo, long zero_hi,
    float* __restrict__ pout, int n)
{
    __shared__ float WpS[DIM_IN * 64];
    __shared__ float EeS[64 * NEXP];
    __shared__ float hS[8][64];
    __shared__ float pS[8][8];
    __shared__ int   cntS[NEXP];

    int tid = threadIdx.x, warp = tid >> 5, lane = tid & 31;
    for (int i = tid; i < DIM_IN * 64; i += 256) WpS[i] = Wp[i];
    for (int i = tid; i < 64 * NEXP; i += 256)   EeS[i] = Ee[i];
    if (tid < NEXP) cntS[tid] = 0;
    if (blockIdx.x == 0 && tid == 0) {
        for (long i = zero_lo; i < zero_hi; i++) outbuf[i] = 0.f;
    }
    __syncthreads();

    const float4 z4 = make_float4(0.f, 0.f, 0.f, 0.f);

    for (int tok = blockIdx.x * 8 + warp; tok < n; tok += gridDim.x * 8) {
        float xr[4];
        #pragma unroll
        for (int i = 0; i < 4; i++) xr[i] = x[(long)tok * DIM_IN + lane + 32 * i];

        reinterpret_cast<float4*>(outbuf + (long)tok * DIM_OUT)[lane] = z4;

        #pragma unroll
        for (int i = 0; i < 4; i++) {
            __nv_bfloat16 hi = __float2bfloat16_rn(xr[i]);
            __nv_bfloat16 lo = __float2bfloat16_rn(xr[i] - __bfloat162float(hi));
            g_xhi[(long)tok * DIM_IN + lane + 32 * i] = hi;
            g_xlo[(long)tok * DIM_IN + lane + 32 * i] = lo;
        }

        float h0 = bp[lane], h1 = bp[lane + 32];
        #pragma unroll
        for (int d = 0; d < DIM_IN; d++) {
            float xd = __shfl_sync(0xffffffffu, xr[d >> 5], d & 31);
            h0 += xd * WpS[d * 64 + lane];
            h1 += xd * WpS[d * 64 + lane + 32];
        }
        hS[warp][lane] = h0;
        hS[warp][lane + 32] = h1;
        __syncwarp();

        if (lane < NEXP) {
            float lg = 0.f;
            #pragma unroll
            for (int e2 = 0; e2 < 64; e2++) lg += hS[warp][e2] * EeS[e2 * NEXP + lane];
            float p = 1.f / (1.f + expf(-lg * 0.2f));   // tau = 5
            pS[warp][lane] = p;
            if (pout) pout[(long)tok * NEXP + lane] = p;
        }
        __syncwarp();

        if (lane == 0) {
            float v0 = -1.f, v1 = -1.f; int i0 = 0, i1 = 0;
            #pragma unroll
            for (int j = 0; j < NEXP; j++) {
                float pv = pS[warp][j];
                if (pv > v0) { v1 = v0; i1 = i0; v0 = pv; i0 = j; }
                else if (pv > v1) { v1 = pv; i1 = j; }
            }
            float s = v0 + v1 + 1e-10f;
            g_tokE[tok] = i0 | (i1 << 8);
            g_tokW[tok] = make_float2(v0 / s, v1 / s);
            atomicAdd(&cntS[i0], 1);
            atomicAdd(&cntS[i1], 1);
        }
        __syncwarp();
    }
    __syncthreads();
    if (tid < NEXP) atomicAdd(&g_counts[tid], cntS[tid]);
}

// ---------------- kernel: scan + tile map ----------------
__global__ void moe_build() {
    if (threadIdx.x == 0) {
        int off = 0, tile = 0;
        for (int e = 0; e < NEXP; e++) {
            int c = g_counts[e];
            g_cursor[e] = off;
            for (int t = 0; t < c && tile < MAXTILES; t += 128) {
                g_tileExpert[tile] = e;
                g_tileStart[tile]  = off + t;
                g_tileRows[tile]   = min(128, c - t);
                tile++;
            }
            off += c;
        }
        g_numTiles = tile;
    }
}

// ---------------- kernel: scatter ----------------
__global__ void __launch_bounds__(256) moe_scatter(int n) {
    __shared__ int cnt[NEXP];
    __shared__ int base[NEXP];
    int tid = threadIdx.x;
    if (tid < NEXP) cnt[tid] = 0;
    __syncthreads();

    int tok = blockIdx.x * 256 + tid;
    int e0 = 0, e1 = 0, r0 = 0, r1 = 0; float2 w = make_float2(0.f, 0.f);
    bool ok = (tok < n);
    if (ok) {
        int e01 = g_tokE[tok];
        w = g_tokW[tok];
        e0 = e01 & 255; e1 = (e01 >> 8) & 255;
        r0 = atomicAdd(&cnt[e0], 1);
        r1 = atomicAdd(&cnt[e1], 1);
    }
    __syncthreads();
    if (tid < NEXP) base[tid] = atomicAdd(&g_cursor[tid], cnt[tid]);
    __syncthreads();
    if (ok) {
        int p0 = base[e0] + r0; g_rowToken[p0] = tok; g_rowW[p0] = w.x;
        int p1 = base[e1] + r1; g_rowToken[p1] = tok; g_rowW[p1] = w.y;
    }
}

// ---------------- kernel: grouped expert GEMM (3xBF16, 4x2 warp tiling) ----------------
using FragA = wmma::fragment<wmma::matrix_a, 16, 16, 16, __nv_bfloat16, wmma::row_major>;
using FragB = wmma::fragment<wmma::matrix_b, 16, 16, 16, __nv_bfloat16, wmma::row_major>;
using FragC = wmma::fragment<wmma::accumulator, 16, 16, 16, float>;

#define LDA 136           // X / W2-chunk planes: 128 rows x 136 bf16
#define LDB 264           // W1 / H planes:       128 rows x 264 bf16
#define STAGE_LD 132
#define SMEM_WMMA ((2 * 128 * LDA + 2 * 128 * LDB) * 2)   // 204800 B

__global__ void __launch_bounds__(256, 1) moe_expert(
    const float* __restrict__ b1, const float* __restrict__ b2,
    float* __restrict__ out)
{
    int tile = blockIdx.x;
    if (tile >= g_numTiles) return;
    int e        = g_tileExpert[tile];
    int rowStart = g_tileStart[tile];
    int nRows    = g_tileRows[tile];

    extern __shared__ __align__(16) unsigned char smraw[];
    __nv_bfloat16* sXhi = (__nv_bfloat16*)smraw;            // 128 x LDA
    __nv_bfloat16* sXlo = sXhi + 128 * LDA;
    __nv_bfloat16* sBhi = sXlo + 128 * LDA;                 // 128 x LDB
    __nv_bfloat16* sBlo = sBhi + 128 * LDB;
    float* stageX = (float*)smraw;                          // aliases sX region (128x132 f32)
    float* stageB = (float*)sBhi;                           // aliases sB region

    __shared__ int   tokS[128];
    __shared__ float wS[128];
    __shared__ float b1s[256];
    __shared__ float b2s[128];

    int tid = threadIdx.x, warp = tid >> 5;
    int wm = warp >> 1, wn = warp & 1;
    int m0 = wm * 32;

    if (tid < 128) {
        int tok = -1; float w = 0.f;
        if (tid < nRows) { tok = g_rowToken[rowStart + tid]; w = g_rowW[rowStart + tid]; }
        tokS[tid] = tok; wS[tid] = w;
        b2s[tid] = b2[(long)e * DIM_OUT + tid];
    }
    b1s[tid] = b1[(long)e * DIM_HID + tid];                 // 256 threads cover 256
    __syncthreads();

    // ---- fill X (gathered bf16 planes) ----
    const uint4* xh4 = (const uint4*)g_xhi;
    const uint4* xl4 = (const uint4*)g_xlo;
    #pragma unroll 4
    for (int i = tid; i < 128 * 16; i += 256) {
        int r = i >> 4, u = i & 15;
        uint4 vh = make_uint4(0, 0, 0, 0), vl = vh;
        int tok = tokS[r];
        if (tok >= 0) { vh = xh4[(long)tok * 16 + u]; vl = xl4[(long)tok * 16 + u]; }
        *reinterpret_cast<uint4*>(&sXhi[r * LDA + u * 8]) = vh;
        *reinterpret_cast<uint4*>(&sXlo[r * LDA + u * 8]) = vl;
    }
    // ---- fill W1 [k=128][n=256] bf16 planes ----
    const uint4* w1h4 = (const uint4*)(g_w1hi + (long)e * DIM_IN * DIM_HID);
    const uint4* w1l4 = (const uint4*)(g_w1lo + (long)e * DIM_IN * DIM_HID);
    #pragma unroll 4
    for (int i = tid; i < 128 * 32; i += 256) {
        int r = i >> 5, u = i & 31;
        *reinterpret_cast<uint4*>(&sBhi[r * LDB + u * 8]) = w1h4[i];
        *reinterpret_cast<uint4*>(&sBlo[r * LDB + u * 8]) = w1l4[i];
    }
    __syncthreads();

    // ---- GEMM1: H[128x256] = X @ W1 ; warp tile 32 x 128 ----
    FragC acc[2][8];
    #pragma unroll
    for (int mi = 0; mi < 2; mi++)
        #pragma unroll
        for (int nt = 0; nt < 8; nt++) wmma::fill_fragment(acc[mi][nt], 0.f);

    int nbase = wn * 128;
    #pragma unroll
    for (int ks = 0; ks < 8; ks++) {
        FragA ahi[2], alo[2];
        #pragma unroll
        for (int mi = 0; mi < 2; mi++) {
            wmma::load_matrix_sync(ahi[mi], &sXhi[(m0 + mi * 16) * LDA + ks * 16], LDA);
            wmma::load_matrix_sync(alo[mi], &sXlo[(m0 + mi * 16) * LDA + ks * 16], LDA);
        }
        #pragma unroll
        for (int nt = 0; nt < 8; nt++) {
            FragB bhi, blo;
            wmma::load_matrix_sync(bhi, &sBhi[(ks * 16) * LDB + nbase + nt * 16], LDB);
            wmma::load_matrix_sync(blo, &sBlo[(ks * 16) * LDB + nbase + nt * 16], LDB);
            #pragma unroll
            for (int mi = 0; mi < 2; mi++) {
                wmma::mma_sync(acc[mi][nt], ahi[mi], bhi, acc[mi][nt]);
                wmma::mma_sync(acc[mi][nt], ahi[mi], blo, acc[mi][nt]);
                wmma::mma_sync(acc[mi][nt], alo[mi], bhi, acc[mi][nt]);
            }
        }
    }
    __syncthreads();   // X and W1 fully consumed

    // ---- H = relu(acc + b1): stage fp32 through sX area, split-bf16 into sB ----
    #pragma unroll
    for (int h = 0; h < 2; h++) {
        if (wn == h) {
            #pragma unroll
            for (int mi = 0; mi < 2; mi++)
                #pragma unroll
                for (int nt = 0; nt < 8; nt++)
                    wmma::store_matrix_sync(&stageX[(m0 + mi * 16) * STAGE_LD + nt * 16],
                                            acc[mi][nt], STAGE_LD, wmma::mem_row_major);
        }
        __syncthreads();
        for (int i = tid; i < 128 * 128; i += 256) {
            int r = i >> 7, c = i & 127;
            float v = stageX[r * STAGE_LD + c] + b1s[h * 128 + c];
            v = v > 0.f ? v : 0.f;
            __nv_bfloat16 hb = __float2bfloat16_rn(v);
            sBhi[r * LDB + h * 128 + c] = hb;
            sBlo[r * LDB + h * 128 + c] = __float2bfloat16_rn(v - __bfloat162float(hb));
        }
        __syncthreads();
    }

    // ---- GEMM2: C[128x128] = H[128x256] @ W2 ; 2 K-chunks of 128 through sX planes ----
    FragC acc2[2][4];
    #pragma unroll
    for (int mi = 0; mi < 2; mi++)
        #pragma unroll
        for (int nt = 0; nt < 4; nt++) wmma::fill_fragment(acc2[mi][nt], 0.f);

    const uint4* w2h4 = (const uint4*)(g_w2hi + (long)e * DIM_HID * DIM_OUT);
    const uint4* w2l4 = (const uint4*)(g_w2lo + (long)e * DIM_HID * DIM_OUT);

    #pragma unroll
    for (int ch = 0; ch < 2; ch++) {
        #pragma unroll 4
        for (int i = tid; i < 128 * 16; i += 256) {       // 128 k-rows x 128 n
            int r = i >> 4, u = i & 15;
            *reinterpret_cast<uint4*>(&sXhi[r * LDA + u * 8]) = w2h4[(ch * 128 + r) * 16 + u];
            *reinterpret_cast<uint4*>(&sXlo[r * LDA + u * 8]) = w2l4[(ch * 128 + r) * 16 + u];
        }
        __syncthreads();
        #pragma unroll
        for (int ks = 0; ks < 8; ks++) {
            FragA ahi[2], alo[2];
            #pragma unroll
            for (int mi = 0; mi < 2; mi++) {
                wmma::load_matrix_sync(ahi[mi], &sBhi[(m0 + mi * 16) * LDB + ch * 128 + ks * 16], LDB);
                wmma::load_matrix_sync(alo[mi], &sBlo[(m0 + mi * 16) * LDB + ch * 128 + ks * 16], LDB);
            }
            #pragma unroll
            for (int nt = 0; nt < 4; nt++) {
                FragB bhi, blo;
                wmma::load_matrix_sync(bhi, &sXhi[(ks * 16) * LDA + wn * 64 + nt * 16], LDA);
                wmma::load_matrix_sync(blo, &sXlo[(ks * 16) * LDA + wn * 64 + nt * 16], LDA);
                #pragma unroll
                for (int mi = 0; mi < 2; mi++) {
                    wmma::mma_sync(acc2[mi][nt], ahi[mi], bhi, acc2[mi][nt]);
                    wmma::mma_sync(acc2[mi][nt], ahi[mi], blo, acc2[mi][nt]);
                    wmma::mma_sync(acc2[mi][nt], alo[mi], bhi, acc2[mi][nt]);
                }
            }
        }
        __syncthreads();
    }

    // ---- epilogue: out[tok] += w * (C + b2) ----
    #pragma unroll
    for (int mi = 0; mi < 2; mi++)
        #pragma unroll
        for (int nt = 0; nt < 4; nt++)
            wmma::store_matrix_sync(&stageB[(m0 + mi * 16) * STAGE_LD + wn * 64 + nt * 16],
                                    acc2[mi][nt], STAGE_LD, wmma::mem_row_major);
    __syncthreads();

    for (int i = tid; i < 128 * DIM_OUT; i += 256) {
        int r = i >> 7, c = i & 127;
        int tok = tokS[r];
        if (tok >= 0)
            atomicAdd(&out[(long)tok * DIM_OUT + c],
                      wS[r] * (stageB[r * STAGE_LD + c] + b2s[c]));
    }
}

// ---------------- launch ----------------
extern "C" void kernel_launch(void* const* d_in, const int* in_sizes, int n_in,
                              void* d_out, int out_size) {
    const float* x  = (const float*)d_in[0];
    const float* Wp = (const float*)d_in[1];
    const float* bp = (const float*)d_in[2];
    const float* Ee = (const float*)d_in[3];
    const float* W1 = (const float*)d_in[4];
    const float* b1 = (const float*)d_in[5];
    const float* W2 = (const float*)d_in[6];
    const float* b2 = (const float*)d_in[7];
    float* out = (float*)d_out;

    int n = in_sizes[0] / DIM_IN;

    float* pout = nullptr;
    long need = (long)n * DIM_OUT + (long)n * NEXP;
    long zlo = (long)n * DIM_OUT, zhi = (long)out_size;
    if ((long)out_size >= need) {
        pout = out + ((long)out_size - (long)n * NEXP);
        zhi = (long)out_size - (long)n * NEXP;
    }

    moe_prep<<<512, 256>>>(W1, W2);
    moe_gate<<<1024, 256>>>(x, Wp, bp, Ee, out, zlo, zhi, pout, n);
    moe_build<<<1, 1>>>();
    moe_scatter<<<(n + 255) / 256, 256>>>(n);

    int tiles = (2 * n + 127) / 128 + NEXP;
    cudaFuncSetAttribute(moe_expert, cudaFuncAttributeMaxDynamicSharedMemorySize, SMEM_WMMA);
    moe_expert<<<tiles, 256, SMEM_WMMA>>>(b1, b2, out);
}

// round 8
// speedup vs baseline: 2.5521x; 1.2189x over previous
#include <cuda_runtime.h>
#include <cuda_bf16.h>
#include <cuda_fp16.h>
#include <mma.h>
#include <cstdint>

using namespace nvcuda;

#define DIM_IN  128
#define DIM_HID 256
#define DIM_OUT 128
#define NEXP    8
#define MAXN    65536
#define MAXROWS (2 * MAXN)
#define MAXTILES (MAXROWS / 128 + NEXP)

#if defined(__CUDA_ARCH__) && (defined(__CUDA_ARCH_FEAT_SM103_ALL) || defined(__CUDA_ARCH_FEAT_SM100_ALL))
#define HAS_TCGEN05 1
#else
#define HAS_TCGEN05 0
#endif

// ---------------- device scratch ----------------
__device__ int    g_counts[NEXP];
__device__ int    g_cursor[NEXP];
__device__ int    g_numTiles;
__device__ int    g_tileExpert[MAXTILES];
__device__ int    g_tileStart[MAXTILES];
__device__ int    g_tileRows[MAXTILES];
__device__ int    g_tokE[MAXN];
__device__ float2 g_tokW[MAXN];
__device__ int    g_rowToken[MAXROWS];
__device__ float  g_rowW[MAXROWS];
__device__ float  g_probe[1024];   // tcgen05 probe scratch (never read)

__device__ __align__(16) __half g_xhi[MAXN * DIM_IN];
__device__ __align__(16) __half g_xlo[MAXN * DIM_IN];
__device__ __align__(16) __half g_w1h[NEXP * DIM_IN * DIM_HID];  // [e][k=128][n=256]
__device__ __align__(16) __half g_w2h[NEXP * DIM_HID * DIM_OUT]; // [e][k=256][n=128]

__device__ __forceinline__ uint32_t packh2(float a, float b) {
    __half2 h = __floats2half2_rn(a, b);
    return *reinterpret_cast<uint32_t*>(&h);
}

// ---------------- kernel: weight fp16 convert + zero counts ----------------
__global__ void __launch_bounds__(256) moe_prep(
    const float* __restrict__ W1, const float* __restrict__ W2)
{
    int idx = blockIdx.x * 256 + threadIdx.x;          // 0 .. 65535
    if (blockIdx.x == 0 && threadIdx.x < NEXP) g_counts[threadIdx.x] = 0;
    if (idx < 65536) {
        float4 v = reinterpret_cast<const float4*>(W1)[idx];
        reinterpret_cast<uint2*>(g_w1h)[idx] = make_uint2(packh2(v.x, v.y), packh2(v.z, v.w));
        float4 w = reinterpret_cast<const float4*>(W2)[idx];
        reinterpret_cast<uint2*>(g_w2h)[idx] = make_uint2(packh2(w.x, w.y), packh2(w.z, w.w));
    }
}

// ---------------- kernel: gate (+ X fp16 split + output zeroing) ----------------
__global__ void __launch_bounds__(256) moe_gate(
    const float* __restrict__ x, const float* __restrict__ Wp,
    const float* __restrict__ bp, const float* __restrict__ Ee,
    float* __restrict__ outbuf, long zero_lo, long zero_hi,
    float* __restrict__ pout, int n)
{
    __shared__ float WpS[DIM_IN * 64];
    __shared__ float EeS[64 * NEXP];
    __shared__ float hS[8][64];
    __shared__ float pS[8][8];
    __shared__ int   cntS[NEXP];

    int tid = threadIdx.x, warp = tid >> 5, lane = tid & 31;
    for (int i = tid; i < DIM_IN * 64; i += 256) WpS[i] = Wp[i];
    for (int i = tid; i < 64 * NEXP; i += 256)   EeS[i] = Ee[i];
    if (tid < NEXP) cntS[tid] = 0;
    if (blockIdx.x == 0 && tid == 0) {
        for (long i = zero_lo; i < zero_hi; i++) outbuf[i] = 0.f;
    }
    __syncthreads();

    const float4 z4 = make_float4(0.f, 0.f, 0.f, 0.f);

    for (int tok = blockIdx.x * 8 + warp; tok < n; tok += gridDim.x * 8) {
        float xr[4];
        #pragma unroll
        for (int i = 0; i < 4; i++) xr[i] = x[(long)tok * DIM_IN + lane + 32 * i];

        reinterpret_cast<float4*>(outbuf + (long)tok * DIM_OUT)[lane] = z4;

        #pragma unroll
        for (int i = 0; i < 4; i++) {
            __half hi = __float2half_rn(xr[i]);
            __half lo = __float2half_rn(xr[i] - __half2float(hi));
            g_xhi[(long)tok * DIM_IN + lane + 32 * i] = hi;
            g_xlo[(long)tok * DIM_IN + lane + 32 * i] = lo;
        }

        float h0 = bp[lane], h1 = bp[lane + 32];
        #pragma unroll
        for (int d = 0; d < DIM_IN; d++) {
            float xd = __shfl_sync(0xffffffffu, xr[d >> 5], d & 31);
            h0 += xd * WpS[d * 64 + lane];
            h1 += xd * WpS[d * 64 + lane + 32];
        }
        hS[warp][lane] = h0;
        hS[warp][lane + 32] = h1;
        __syncwarp();

        if (lane < NEXP) {
            float lg = 0.f;
            #pragma unroll
            for (int e2 = 0; e2 < 64; e2++) lg += hS[warp][e2] * EeS[e2 * NEXP + lane];
            float p = 1.f / (1.f + expf(-lg * 0.2f));   // tau = 5
            pS[warp][lane] = p;
            if (pout) pout[(long)tok * NEXP + lane] = p;
        }
        __syncwarp();

        if (lane == 0) {
            float v0 = -1.f, v1 = -1.f; int i0 = 0, i1 = 0;
            #pragma unroll
            for (int j = 0; j < NEXP; j++) {
                float pv = pS[warp][j];
                if (pv > v0) { v1 = v0; i1 = i0; v0 = pv; i0 = j; }
                else if (pv > v1) { v1 = pv; i1 = j; }
            }
            float s = v0 + v1 + 1e-10f;
            g_tokE[tok] = i0 | (i1 << 8);
            g_tokW[tok] = make_float2(v0 / s, v1 / s);
            atomicAdd(&cntS[i0], 1);
            atomicAdd(&cntS[i1], 1);
        }
        __syncwarp();
    }
    __syncthreads();
    if (tid < NEXP) atomicAdd(&g_counts[tid], cntS[tid]);
}

// ---------------- kernel: scan + tile map ----------------
__global__ void moe_build() {
    if (threadIdx.x == 0) {
        int off = 0, tile = 0;
        for (int e = 0; e < NEXP; e++) {
            int c = g_counts[e];
            g_cursor[e] = off;
            for (int t = 0; t < c && tile < MAXTILES; t += 128) {
                g_tileExpert[tile] = e;
                g_tileStart[tile]  = off + t;
                g_tileRows[tile]   = min(128, c - t);
                tile++;
            }
            off += c;
        }
        g_numTiles = tile;
    }
}

// ---------------- kernel: scatter ----------------
__global__ void __launch_bounds__(256) moe_scatter(int n) {
    __shared__ int cnt[NEXP];
    __shared__ int base[NEXP];
    int tid = threadIdx.x;
    if (tid < NEXP) cnt[tid] = 0;
    __syncthreads();

    int tok = blockIdx.x * 256 + tid;
    int e0 = 0, e1 = 0, r0 = 0, r1 = 0; float2 w = make_float2(0.f, 0.f);
    bool ok = (tok < n);
    if (ok) {
        int e01 = g_tokE[tok];
        w = g_tokW[tok];
        e0 = e01 & 255; e1 = (e01 >> 8) & 255;
        r0 = atomicAdd(&cnt[e0], 1);
        r1 = atomicAdd(&cnt[e1], 1);
    }
    __syncthreads();
    if (tid < NEXP) base[tid] = atomicAdd(&g_cursor[tid], cnt[tid]);
    __syncthreads();
    if (ok) {
        int p0 = base[e0] + r0; g_rowToken[p0] = tok; g_rowW[p0] = w.x;
        int p1 = base[e1] + r1; g_rowToken[p1] = tok; g_rowW[p1] = w.y;
    }
}

// ---------------- kernel: grouped expert GEMM (2-pass fp16 split) ----------------
using FragA = wmma::fragment<wmma::matrix_a, 16, 16, 16, __half, wmma::row_major>;
using FragB = wmma::fragment<wmma::matrix_b, 16, 16, 16, __half, wmma::row_major>;
using FragC = wmma::fragment<wmma::accumulator, 16, 16, 16, float>;

#define LDA 136           // X planes / W2 chunk planes: 128 x 136 half
#define LDB 264           // W1 / H planes:              128 x 264 half
#define STAGE_LD 132
#define SMEM_WMMA ((2 * 128 * LDA + 2 * 128 * LDB) * 2)   // 204800 B

__global__ void __launch_bounds__(256, 1) moe_expert(
    const float* __restrict__ b1, const float* __restrict__ b2,
    float* __restrict__ out)
{
    int tile = blockIdx.x;
    if (tile >= g_numTiles) return;
    int e        = g_tileExpert[tile];
    int rowStart = g_tileStart[tile];
    int nRows    = g_tileRows[tile];

    extern __shared__ __align__(16) unsigned char smraw[];
    __half* sXhi = (__half*)smraw;                 // 128 x LDA (X hi / W2 chunk0)
    __half* sXlo = sXhi + 128 * LDA;               // 128 x LDA (X lo / W2 chunk1)
    __half* sHhi = sXlo + 128 * LDA;               // 128 x LDB (W1 / H hi)
    __half* sHlo = sHhi + 128 * LDB;               // 128 x LDB (H lo)
    float* stageX = (float*)smraw;                 // fp32 stage aliasing sX region
    float* stageB = (float*)sHhi;                  // fp32 stage aliasing sH region

    __shared__ int   tokS[128];
    __shared__ float wS[128];
    __shared__ float b1s[256];
    __shared__ float b2s[128];

    int tid = threadIdx.x, warp = tid >> 5;
    int wm = warp >> 1, wn = warp & 1;
    int m0 = wm * 32;

    if (tid < 128) {
        int tok = -1; float w = 0.f;
        if (tid < nRows) { tok = g_rowToken[rowStart + tid]; w = g_rowW[rowStart + tid]; }
        tokS[tid] = tok; wS[tid] = w;
        b2s[tid] = b2[(long)e * DIM_OUT + tid];
    }
    b1s[tid] = b1[(long)e * DIM_HID + tid];
    __syncthreads();

    // ---- fill X (gathered fp16 planes) ----
    const uint4* xh4 = (const uint4*)g_xhi;
    const uint4* xl4 = (const uint4*)g_xlo;
    #pragma unroll 4
    for (int i = tid; i < 128 * 16; i += 256) {
        int r = i >> 4, u = i & 15;
        uint4 vh = make_uint4(0, 0, 0, 0), vl = vh;
        int tok = tokS[r];
        if (tok >= 0) { vh = xh4[(long)tok * 16 + u]; vl = xl4[(long)tok * 16 + u]; }
        *reinterpret_cast<uint4*>(&sXhi[r * LDA + u * 8]) = vh;
        *reinterpret_cast<uint4*>(&sXlo[r * LDA + u * 8]) = vl;
    }
    // ---- fill W1 [k=128][n=256] single fp16 plane (into sHhi) ----
    const uint4* w1h4 = (const uint4*)(g_w1h + (long)e * DIM_IN * DIM_HID);
    #pragma unroll 4
    for (int i = tid; i < 128 * 32; i += 256) {
        int r = i >> 5, u = i & 31;
        *reinterpret_cast<uint4*>(&sHhi[r * LDB + u * 8]) = w1h4[i];
    }
    __syncthreads();

    // ---- GEMM1: H[128x256] = (Xhi + Xlo) @ W1 ; warp tile 32 x 128 ----
    FragC acc[2][8];
    #pragma unroll
    for (int mi = 0; mi < 2; mi++)
        #pragma unroll
        for (int nt = 0; nt < 8; nt++) wmma::fill_fragment(acc[mi][nt], 0.f);

    int nbase = wn * 128;
    #pragma unroll
    for (int ks = 0; ks < 8; ks++) {
        FragA ahi[2], alo[2];
        #pragma unroll
        for (int mi = 0; mi < 2; mi++) {
            wmma::load_matrix_sync(ahi[mi], &sXhi[(m0 + mi * 16) * LDA + ks * 16], LDA);
            wmma::load_matrix_sync(alo[mi], &sXlo[(m0 + mi * 16) * LDA + ks * 16], LDA);
        }
        #pragma unroll
        for (int nt = 0; nt < 8; nt++) {
            FragB b;
            wmma::load_matrix_sync(b, &sHhi[(ks * 16) * LDB + nbase + nt * 16], LDB);
            #pragma unroll
            for (int mi = 0; mi < 2; mi++) {
                wmma::mma_sync(acc[mi][nt], ahi[mi], b, acc[mi][nt]);
                wmma::mma_sync(acc[mi][nt], alo[mi], b, acc[mi][nt]);
            }
        }
    }
    __syncthreads();   // X and W1 fully consumed

    // ---- H = relu(acc + b1): stage fp32 through sX area, split-fp16 into sH planes ----
    #pragma unroll
    for (int h = 0; h < 2; h++) {
        if (wn == h) {
            #pragma unroll
            for (int mi = 0; mi < 2; mi++)
                #pragma unroll
                for (int nt = 0; nt < 8; nt++)
                    wmma::store_matrix_sync(&stageX[(m0 + mi * 16) * STAGE_LD + nt * 16],
                                            acc[mi][nt], STAGE_LD, wmma::mem_row_major);
        }
        __syncthreads();
        for (int i = tid; i < 128 * 128; i += 256) {
            int r = i >> 7, c = i & 127;
            float v = stageX[r * STAGE_LD + c] + b1s[h * 128 + c];
            v = v > 0.f ? v : 0.f;
            __half hh = __float2half_rn(v);
            sHhi[r * LDB + h * 128 + c] = hh;
            sHlo[r * LDB + h * 128 + c] = __float2half_rn(v - __half2float(hh));
        }
        __syncthreads();
    }

    // ---- fill BOTH W2 K-chunks (chunk0 -> sXhi plane, chunk1 -> sXlo plane) ----
    const uint4* w2h4 = (const uint4*)(g_w2h + (long)e * DIM_HID * DIM_OUT);
    #pragma unroll 4
    for (int i = tid; i < 2 * 128 * 16; i += 256) {
        int ch = i >= 128 * 16;
        int j = i - ch * 128 * 16;
        int r = j >> 4, u = j & 15;
        __half* dst = ch ? sXlo : sXhi;
        *reinterpret_cast<uint4*>(&dst[r * LDA + u * 8]) = w2h4[(ch * 128 + r) * 16 + u];
    }
    __syncthreads();

    // ---- GEMM2: C[128x128] = (Hhi + Hlo) @ W2 ; both chunks, no mid-barrier ----
    FragC acc2[2][4];
    #pragma unroll
    for (int mi = 0; mi < 2; mi++)
        #pragma unroll
        for (int nt = 0; nt < 4; nt++) wmma::fill_fragment(acc2[mi][nt], 0.f);

    #pragma unroll
    for (int ch = 0; ch < 2; ch++) {
        const __half* Bp = ch ? sXlo : sXhi;
        #pragma unroll
        for (int ks = 0; ks < 8; ks++) {
            FragA ahi[2], alo[2];
            #pragma unroll
            for (int mi = 0; mi < 2; mi++) {
                wmma::load_matrix_sync(ahi[mi], &sHhi[(m0 + mi * 16) * LDB + ch * 128 + ks * 16], LDB);
                wmma::load_matrix_sync(alo[mi], &sHlo[(m0 + mi * 16) * LDB + ch * 128 + ks * 16], LDB);
            }
            #pragma unroll
            for (int nt = 0; nt < 4; nt++) {
                FragB b;
                wmma::load_matrix_sync(b, &Bp[(ks * 16) * LDA + wn * 64 + nt * 16], LDA);
                #pragma unroll
                for (int mi = 0; mi < 2; mi++) {
                    wmma::mma_sync(acc2[mi][nt], ahi[mi], b, acc2[mi][nt]);
                    wmma::mma_sync(acc2[mi][nt], alo[mi], b, acc2[mi][nt]);
                }
            }
        }
    }
    __syncthreads();   // H planes fully consumed

    // ---- epilogue: out[tok] += w * (C + b2) ----
    #pragma unroll
    for (int mi = 0; mi < 2; mi++)
        #pragma unroll
        for (int nt = 0; nt < 4; nt++)
            wmma::store_matrix_sync(&stageB[(m0 + mi * 16) * STAGE_LD + wn * 64 + nt * 16],
                                    acc2[mi][nt], STAGE_LD, wmma::mem_row_major);
    __syncthreads();

    for (int i = tid; i < 128 * DIM_OUT; i += 256) {
        int r = i >> 7, c = i & 127;
        int tok = tokS[r];
        if (tok >= 0)
            atomicAdd(&out[(long)tok * DIM_OUT + c],
                      wS[r] * (stageB[r * STAGE_LD + c] + b2s[c]));
    }
}

// ================= tcgen05 probe (near-verbatim test_mma_iter, 1 CTA) =================
#if HAS_TCGEN05
__device__ __forceinline__ uint32_t smem_u32(const void* p) {
    uint32_t a;
    asm("{ .reg .u64 t; cvta.to.shared.u64 t, %1; cvt.u32.u64 %0, t; }" : "=r"(a) : "l"(p));
    return a;
}
__device__ __forceinline__ uint32_t elect_one() {
    uint32_t p;
    asm volatile("{ .reg .pred p; elect.sync _|p, 0xFFFFFFFF; selp.b32 %0, 1, 0, p; }" : "=r"(p));
    return p;
}
#define TC_ALLOC(sm, n)  asm volatile("tcgen05.alloc.cta_group::1.sync.aligned.shared::cta.b32 [%0], %1;" :: "r"(sm), "r"(n) : "memory")
#define TC_DEALLOC(t, n) asm volatile("tcgen05.dealloc.cta_group::1.sync.aligned.b32 %0, %1;" :: "r"(t), "r"(n))
#define TC_COMMIT(mb)    asm volatile("tcgen05.commit.cta_group::1.mbarrier::arrive::one.shared::cluster.b64 [%0];" :: "r"(mb) : "memory")
#define TC_WAIT_LD()     asm volatile("tcgen05.wait::ld.sync.aligned;" ::: "memory")
#define TC_WAIT_ST()     asm volatile("tcgen05.wait::st.sync.aligned;" ::: "memory")
#define TC_FENCE_AFTER() asm volatile("tcgen05.fence::after_thread_sync;" ::: "memory")
#define MBAR_INIT(mb, c) asm volatile("mbarrier.init.shared.b64 [%0], %1;" :: "r"(mb), "r"(c) : "memory")
#define MBAR_WAIT(mb, ph) do {                                            \
    uint32_t _m = (mb), _p = (ph), _d;                                    \
    asm volatile("{ .reg .pred p; mbarrier.try_wait.parity.acquire.cta.shared::cta.b64 p, [%1], %2; selp.b32 %0, 1, 0, p; }" \
        : "=r"(_d) : "r"(_m), "r"(_p) : "memory");                        \
    if (!_d) {                                                            \
        asm volatile("{ .reg .pred P1; WL%=: mbarrier.try_wait.parity.acquire.cta.shared::cta.b64 P1, [%0], %1, 0x989680; @P1 bra.uni WD%=; bra.uni WL%=; WD%=: }" \
            :: "r"(_m), "r"(_p) : "memory");                              \
    }                                                                     \
} while (0)
#define TC_LD_X32(r, t)                                                   \
    asm volatile("tcgen05.ld.sync.aligned.32x32b.x32.b32 "                \
        "{%0,%1,%2,%3,%4,%5,%6,%7,%8,%9,%10,%11,%12,%13,%14,%15,"        \
        "%16,%17,%18,%19,%20,%21,%22,%23,%24,%25,%26,%27,%28,%29,%30,%31}, [%32];" \
        : "=r"((r)[0]),"=r"((r)[1]),"=r"((r)[2]),"=r"((r)[3]),"=r"((r)[4]),"=r"((r)[5]),"=r"((r)[6]),"=r"((r)[7]), \
          "=r"((r)[8]),"=r"((r)[9]),"=r"((r)[10]),"=r"((r)[11]),"=r"((r)[12]),"=r"((r)[13]),"=r"((r)[14]),"=r"((r)[15]), \
          "=r"((r)[16]),"=r"((r)[17]),"=r"((r)[18]),"=r"((r)[19]),"=r"((r)[20]),"=r"((r)[21]),"=r"((r)[22]),"=r"((r)[23]), \
          "=r"((r)[24]),"=r"((r)[25]),"=r"((r)[26]),"=r"((r)[27]),"=r"((r)[28]),"=r"((r)[29]),"=r"((r)[30]),"=r"((r)[31]) \
        : "r"(t))
#define TC_ST_X64(t, r)                                                   \
    asm volatile("tcgen05.st.sync.aligned.32x32b.x64.b32 [%0], "          \
        "{%1,%2,%3,%4,%5,%6,%7,%8,%9,%10,%11,%12,%13,%14,%15,%16,"       \
        "%17,%18,%19,%20,%21,%22,%23,%24,%25,%26,%27,%28,%29,%30,%31,%32," \
        "%33,%34,%35,%36,%37,%38,%39,%40,%41,%42,%43,%44,%45,%46,%47,%48," \
        "%49,%50,%51,%52,%53,%54,%55,%56,%57,%58,%59,%60,%61,%62,%63,%64};" \
        :: "r"(t),                                                        \
           "r"((r)[0]),"r"((r)[1]),"r"((r)[2]),"r"((r)[3]),"r"((r)[4]),"r"((r)[5]),"r"((r)[6]),"r"((r)[7]), \
           "r"((r)[8]),"r"((r)[9]),"r"((r)[10]),"r"((r)[11]),"r"((r)[12]),"r"((r)[13]),"r"((r)[14]),"r"((r)[15]), \
           "r"((r)[16]),"r"((r)[17]),"r"((r)[18]),"r"((r)[19]),"r"((r)[20]),"r"((r)[21]),"r"((r)[22]),"r"((r)[23]), \
           "r"((r)[24]),"r"((r)[25]),"r"((r)[26]),"r"((r)[27]),"r"((r)[28]),"r"((r)[29]),"r"((r)[30]),"r"((r)[31]), \
           "r"((r)[32]),"r"((r)[33]),"r"((r)[34]),"r"((r)[35]),"r"((r)[36]),"r"((r)[37]),"r"((r)[38]),"r"((r)[39]), \
           "r"((r)[40]),"r"((r)[41]),"r"((r)[42]),"r"((r)[43]),"r"((r)[44]),"r"((r)[45]),"r"((r)[46]),"r"((r)[47]), \
           "r"((r)[48]),"r"((r)[49]),"r"((r)[50]),"r"((r)[51]),"r"((r)[52]),"r"((r)[53]),"r"((r)[54]),"r"((r)[55]), \
           "r"((r)[56]),"r"((r)[57]),"r"((r)[58]),"r"((r)[59]),"r"((r)[60]),"r"((r)[61]),"r"((r)[62]),"r"((r)[63]) \
        : "memory")

__device__ __forceinline__ void mma_f16_ts(uint32_t d, uint32_t a_tmem, uint64_t bd,
                                           uint32_t idesc, bool en) {
    uint32_t e = en ? 1u : 0u;
    asm volatile(
        "{\n\t.reg .pred p;\n\tsetp.ne.u32 p, %5, 0;\n\t"
        "tcgen05.mma.cta_group::1.kind::f16 [%0], [%1], %2, %3, {%4, %4, %4, %4}, p;\n\t}"
        :: "r"(d), "r"(a_tmem), "l"(bd), "r"(idesc), "r"(0u), "r"(e) : "memory");
}
static constexpr uint64_t DESC_BASE =
    (uint64_t(2) << 61) | (uint64_t(1) << 46) | (uint64_t(64) << 32) | (uint64_t(1) << 16);
__device__ __forceinline__ uint64_t mkdesc(uint32_t a) {
    return DESC_BASE | ((uint64_t)(a >> 4) & 0x3FFF);
}
#endif  // HAS_TCGEN05

__global__ void __cluster_dims__(1, 1, 1) moe_tc_probe() {
#if HAS_TCGEN05
    // Verbatim test_mma_iter flow: M=128, N=32, K=128 bf16 TS MMA.
    extern __shared__ unsigned char praw[];
    unsigned char* sm = (unsigned char*)(((uintptr_t)praw + 1023) & ~(uintptr_t)1023);
    uint32_t smb = smem_u32(sm);
    __shared__ uint32_t tmemS;
    __shared__ __align__(8) unsigned long long mbar;
    int tid = threadIdx.x, wid = tid >> 5, lid = tid & 31;

    if (wid == 0) { TC_ALLOC(smem_u32(&tmemS), 512); }
    __syncthreads();
    uint32_t tmem = tmemS;

    // zero + fill B (32 rows x 128 cols bf16, blocked atom layout, 4 atom-rows)
    for (int i = tid; i < 2048; i += 128) ((uint32_t*)sm)[i] = 0;
    __syncthreads();
    for (int i = tid; i < 32 * 128; i += 128) {
        int row = i >> 7, col = i & 127;
        float v = 0.01f * ((i * 11 + 5) % 29 - 14);
        uint32_t bo = ((uint32_t)((col >> 6) * 4 + (row >> 3)) << 10)
                    + ((uint32_t)(row & 7) << 7) + ((uint32_t)(col & 63) << 1);
        bo ^= (bo >> 3) & 0x70;
        *(__nv_bfloat16*)(sm + bo) = __float2bfloat16(v);
    }
    __syncthreads();

    // A row (tid) -> TMEM cols 0..63 (bf16 pairs)
    {
        uint32_t a[64];
        #pragma unroll
        for (int u = 0; u < 64; u++) {
            int i0 = tid * 128 + 2 * u, i1 = i0 + 1;
            __nv_bfloat16 b0 = __float2bfloat16(0.01f * ((i0 * 7 + 3) % 31 - 15));
            __nv_bfloat16 b1 = __float2bfloat16(0.01f * ((i1 * 7 + 3) % 31 - 15));
            a[u] = (uint32_t)__bfloat16_as_ushort(b0) | ((uint32_t)__bfloat16_as_ushort(b1) << 16);
        }
        TC_ST_X64(tmem + ((uint32_t)(tid >> 5) << 21), a);
        TC_WAIT_ST();
    }
    __syncthreads();

    if (wid == 0) {
        if (elect_one()) { MBAR_INIT(smem_u32(&mbar), 1); }
        __syncwarp();
        uint64_t bd = mkdesc(smb);
        if (elect_one()) {
            #pragma unroll
            for (int i = 0; i < 8; i++) {
                uint64_t off = (uint64_t)((i >> 2) * 256 + (i & 3) * 2);
                mma_f16_ts(tmem + 64, tmem + i * 8, bd + off, 0x8080490u, i > 0);
            }
            TC_COMMIT(smem_u32(&mbar));
        }
        __syncwarp();
        MBAR_WAIT(smem_u32(&mbar), 0);
        TC_FENCE_AFTER();
        uint32_t d[32];
        TC_LD_X32(d, tmem + 64);
        TC_WAIT_LD();
        for (int c = 0; c < 32; c++) g_probe[lid * 32 + c] = __uint_as_float(d[c]);
        if (elect_one()) {
            asm volatile("mbarrier.inval.shared.b64 [%0];" :: "r"(smem_u32(&mbar)) : "memory");
        }
        TC_DEALLOC(tmem, 512);
    }
#endif
}

// ---------------- launch ----------------
extern "C" void kernel_launch(void* const* d_in, const int* in_sizes, int n_in,
                              void* d_out, int out_size) {
    const float* x  = (const float*)d_in[0];
    const float* Wp = (const float*)d_in[1];
    const float* bp = (const float*)d_in[2];
    const float* Ee = (const float*)d_in[3];
    const float* W1 = (const float*)d_in[4];
    const float* b1 = (const float*)d_in[5];
    const float* W2 = (const float*)d_in[6];
    const float* b2 = (const float*)d_in[7];
    float* out = (float*)d_out;

    int n = in_sizes[0] / DIM_IN;

    float* pout = nullptr;
    long need = (long)n * DIM_OUT + (long)n * NEXP;
    long zlo = (long)n * DIM_OUT, zhi = (long)out_size;
    if ((long)out_size >= need) {
        pout = out + ((long)out_size - (long)n * NEXP);
        zhi = (long)out_size - (long)n * NEXP;
    }

    moe_prep<<<256, 256>>>(W1, W2);
    moe_gate<<<1024, 256>>>(x, Wp, bp, Ee, out, zlo, zhi, pout, n);
    moe_build<<<1, 1>>>();
    moe_scatter<<<(n + 255) / 256, 256>>>(n);

    int tiles = (2 * n + 127) / 128 + NEXP;
    cudaFuncSetAttribute(moe_expert, cudaFuncAttributeMaxDynamicSharedMemorySize, SMEM_WMMA);
    moe_expert<<<tiles, 256, SMEM_WMMA>>>(b1, b2, out);

    moe_tc_probe<<<1, 128, 16384>>>();
}